// round 4
// baseline (speedup 1.0000x reference)
#include <cuda_runtime.h>
#include <cstdint>

#define NLEV   3
#define KCODES 512
#define DIM    1024
#define NTOK   65536           // 16 * 4096
#define DECAY  0.99f
#define OMD    0.01f
#define EPSV   1e-5f

typedef unsigned long long ull;

// ---- scratch (__device__ globals: the sanctioned no-alloc path) ----
static __device__ __align__(16) float g_residual[(size_t)NTOK * DIM];  // 268 MB
static __device__ __align__(16) float g_sums[NLEV * KCODES * DIM];     // 6 MB
static __device__ float  g_counts[NLEV * KCODES];
static __device__ float  g_c2[NLEV * KCODES];
static __device__ float  g_cs[NLEV * KCODES];
static __device__ float  g_n[NLEV];
static __device__ double g_loss_acc[NLEV];
static __device__ int    g_idx[NTOK];

// packed fp32x2 FMA: c.lo += a.lo*b.lo ; c.hi += a.hi*b.hi  (exact fp32 per lane)
__device__ __forceinline__ void ffma2(ull& c, ull a, ull b) {
    asm("fma.rn.f32x2 %0, %1, %2, %0;" : "+l"(c) : "l"(a), "l"(b));
}
// 16B async copy global->shared (L2-resident path)
__device__ __forceinline__ void cp16(float* s, const float* g) {
    unsigned a = (unsigned)__cvta_generic_to_shared(s);
    asm volatile("cp.async.cg.shared.global [%0], [%1], 16;" :: "r"(a), "l"(g));
}
__device__ __forceinline__ void cp_commit() { asm volatile("cp.async.commit_group;"); }
__device__ __forceinline__ void cp_wait0()  { asm volatile("cp.async.wait_group 0;"); }
// vectorized float4 reduction to global
__device__ __forceinline__ void red4(float* p, float4 v) {
    asm volatile("red.global.add.v4.f32 [%0], {%1,%2,%3,%4};"
                 :: "l"(p), "f"(v.x), "f"(v.y), "f"(v.z), "f"(v.w) : "memory");
}

union U4 { float4 f; ull u[2]; };
union U2 { ull u; float f[2]; };

// ---------------------------------------------------------------- zero scratch
__global__ void k_zero() {
    int i = blockIdx.x * blockDim.x + threadIdx.x;
    if (i < NLEV * KCODES * DIM) g_sums[i] = 0.f;
    if (i < NLEV * KCODES)       g_counts[i] = 0.f;
    if (i < NLEV)                g_loss_acc[i] = 0.0;
}

// ---------------------------------------------------------------- ||C_k||^2
__global__ void k_c2(const float* __restrict__ codebooks) {
    int w    = (blockIdx.x * blockDim.x + threadIdx.x) >> 5;
    int lane = threadIdx.x & 31;
    if (w >= NLEV * KCODES) return;
    const float* row = codebooks + (size_t)w * DIM;
    float s = 0.f;
#pragma unroll
    for (int it = 0; it < DIM / 128; it++) {
        float4 v = *(const float4*)(row + lane * 4 + it * 128);
        s += v.x * v.x + v.y * v.y + v.z * v.z + v.w * v.w;
    }
#pragma unroll
    for (int o = 16; o; o >>= 1) s += __shfl_xor_sync(0xffffffffu, s, o);
    if (lane == 0) g_c2[w] = s;
}

// ---------------------------------------------------------------- assign (argmin)
// Block tile: 64 tokens x 128 codes; 256 threads; per-thread 4 tok x 8 codes,
// f32x2-packed accumulators. cp.async double-buffered D-chunks of 32.
#define ST_STRIDE (64 * 4 + 4)     // 260 floats per d-quad row
#define SC_STRIDE (128 * 4 + 4)    // 516 floats per d-quad row
#define ST_BUF (8 * ST_STRIDE)
#define SC_BUF (8 * SC_STRIDE)
#define NITER 128                  // 4 code-tiles * 32 d-chunks

__global__ void __launch_bounds__(256, 2) k_assign(int level,
                                                   const float* __restrict__ z_e,
                                                   const float* __restrict__ codebooks,
                                                   float* __restrict__ out_idx) {
    const float* resid = level ? g_residual : z_e;
    const float* cb    = codebooks + (size_t)level * KCODES * DIM;
    const float* c2    = g_c2 + level * KCODES;
    const int t0 = blockIdx.x * 64;

    extern __shared__ float smem[];
    float* sT  = smem;                       // 2 * ST_BUF
    float* sC  = smem + 2 * ST_BUF;          // 2 * SC_BUF
    float* sr2 = smem + 2 * ST_BUF + 2 * SC_BUF;

    const int tid  = threadIdx.x;
    const int warp = tid >> 5, lane = tid & 31;

    // per-token ||r||^2
    for (int t = warp; t < 64; t += 8) {
        const float* r = resid + (size_t)(t0 + t) * DIM + lane * 4;
        float s = 0.f;
#pragma unroll
        for (int it = 0; it < 8; it++) {
            float4 v = *(const float4*)(r + it * 128);
            s += v.x * v.x + v.y * v.y + v.z * v.z + v.w * v.w;
        }
#pragma unroll
        for (int o = 16; o; o >>= 1) s += __shfl_xor_sync(0xffffffffu, s, o);
        if (lane == 0) sr2[t] = s;
    }

    const int tx = tid & 15;   // code lane
    const int ty = tid >> 4;   // token group
    const int ldrow = tid >> 3, lddq = tid & 7;   // staging decomposition

    float cmin[4];
    int   cidx[4];
#pragma unroll
    for (int i = 0; i < 4; i++) { cmin[i] = 3.4e38f; cidx[i] = 0; }

    // stage iteration it = ct*32 + dc into buffer b
    auto stage = [&](int it, int b) {
        const int ct = it >> 5, dc = it & 31;
        // T: 512 float4 slots (2/thread)
#pragma unroll
        for (int i = 0; i < 2; i++) {
            int tok = ldrow + i * 32;
            cp16(&sT[b * ST_BUF + lddq * ST_STRIDE + tok * 4],
                 resid + (size_t)(t0 + tok) * DIM + dc * 32 + lddq * 4);
        }
        // C: 1024 float4 slots (4/thread)
#pragma unroll
        for (int i = 0; i < 4; i++) {
            int code = ldrow + i * 32;
            cp16(&sC[b * SC_BUF + lddq * SC_STRIDE + code * 4],
                 cb + (size_t)(ct * 128 + code) * DIM + dc * 32 + lddq * 4);
        }
        cp_commit();
    };

    stage(0, 0);

    ull acc[4][8];
#pragma unroll
    for (int i = 0; i < 4; i++)
#pragma unroll
        for (int j = 0; j < 8; j++) acc[i][j] = 0ull;

    for (int k = 0; k < NITER; k++) {
        const int b = k & 1;
        cp_wait0();
        __syncthreads();                 // buf b visible; everyone done reading buf b^1
        if (k + 1 < NITER) stage(k + 1, b ^ 1);

#pragma unroll
        for (int dq = 0; dq < 8; dq++) {
            U4 A[4];
#pragma unroll
            for (int i = 0; i < 4; i++)
                A[i].f = *(const float4*)&sT[b * ST_BUF + dq * ST_STRIDE + (ty * 4 + i) * 4];
#pragma unroll
            for (int j = 0; j < 8; j++) {
                U4 B;
                B.f = *(const float4*)&sC[b * SC_BUF + dq * SC_STRIDE + (j * 16 + tx) * 4];
#pragma unroll
                for (int i = 0; i < 4; i++) {
                    ffma2(acc[i][j], A[i].u[0], B.u[0]);
                    ffma2(acc[i][j], A[i].u[1], B.u[1]);
                }
            }
        }

        if ((k & 31) == 31) {
            // end of a 128-code tile: distances + running argmin
            const int ct = k >> 5;
#pragma unroll
            for (int i = 0; i < 4; i++) {
                float r2v = sr2[ty * 4 + i];
                float mv = 3.4e38f; int mi = 0;
#pragma unroll
                for (int j = 0; j < 8; j++) {
                    U2 a; a.u = acc[i][j];
                    float dot = a.f[0] + a.f[1];
                    int id = ct * 128 + j * 16 + tx;
                    float dd = r2v - 2.f * dot + __ldg(c2 + id);
                    if (dd < mv) { mv = dd; mi = id; }
                    acc[i][j] = 0ull;
                }
#pragma unroll
                for (int off = 8; off; off >>= 1) {   // butterfly within 16 tx lanes
                    float ov = __shfl_xor_sync(0xffffffffu, mv, off);
                    int   oi = __shfl_xor_sync(0xffffffffu, mi, off);
                    if (ov < mv || (ov == mv && oi < mi)) { mv = ov; mi = oi; }
                }
                if (mv < cmin[i]) { cmin[i] = mv; cidx[i] = mi; }
            }
        }
    }

    if (tx == 0) {
#pragma unroll
        for (int i = 0; i < 4; i++) {
            int tok = t0 + 4 * ty + i;
            g_idx[tok] = cidx[i];
            out_idx[(size_t)level * NTOK + tok] = (float)cidx[i];
        }
    }
}

// ---------------------------------------------------------------- update
// 4 tokens per block; 64 threads/token, 16 floats/thread; red.v4 scatter.
__global__ void __launch_bounds__(256) k_update(int level,
                                                const float* __restrict__ z_e,
                                                const float* __restrict__ codebooks,
                                                float* __restrict__ out_zq) {
    const int tid = threadIdx.x;
    const int tok = blockIdx.x * 4 + (tid >> 6);
    const int d   = (tid & 63) * 16;
    const float* rin = level ? g_residual : z_e;
    const int idx = g_idx[tok];
    const float* q = codebooks + ((size_t)level * KCODES + idx) * DIM + d;
    const float* r = rin + (size_t)tok * DIM + d;
    float* sums = g_sums + ((size_t)level * KCODES + idx) * DIM + d;
    float* rout = g_residual + (size_t)tok * DIM + d;
    float* zo   = out_zq + (size_t)tok * DIM + d;

    float ls = 0.f;
#pragma unroll
    for (int v = 0; v < 4; v++) {
        float4 rv = *(const float4*)(r + v * 4);
        float4 qv = *(const float4*)(q + v * 4);
        float4 rq = make_float4(rv.x - qv.x, rv.y - qv.y, rv.z - qv.z, rv.w - qv.w);
        *(float4*)(rout + v * 4) = rq;
        if (level) {
            float4 z = *(const float4*)(zo + v * 4);
            z.x += qv.x; z.y += qv.y; z.z += qv.z; z.w += qv.w;
            *(float4*)(zo + v * 4) = z;
        } else {
            *(float4*)(zo + v * 4) = qv;
        }
        red4(sums + v * 4, rv);
        ls += rq.x * rq.x + rq.y * rq.y + rq.z * rq.z + rq.w * rq.w;
    }
    if ((tid & 63) == 0) atomicAdd(g_counts + level * KCODES + idx, 1.0f);

    // block loss reduction -> one double atomic
#pragma unroll
    for (int o = 16; o; o >>= 1) ls += __shfl_xor_sync(0xffffffffu, ls, o);
    __shared__ float red[8];
    const int warp = tid >> 5, lane = tid & 31;
    if (lane == 0) red[warp] = ls;
    __syncthreads();
    if (tid < 8) {
        float v = red[tid];
#pragma unroll
        for (int o = 4; o; o >>= 1) v += __shfl_xor_sync(0xffu, v, o);
        if (tid == 0) atomicAdd(&g_loss_acc[level], (double)v);
    }
}

// ---------------------------------------------------------------- cs + n
__global__ void k_csn(const float* __restrict__ ema_cluster) {
    const int l = blockIdx.x;
    const int k = threadIdx.x;   // 512 threads
    float cs = DECAY * ema_cluster[l * KCODES + k] + OMD * g_counts[l * KCODES + k];
    g_cs[l * KCODES + k] = cs;
    float s = cs;
#pragma unroll
    for (int o = 16; o; o >>= 1) s += __shfl_xor_sync(0xffffffffu, s, o);
    __shared__ float red[16];
    const int warp = threadIdx.x >> 5, lane = threadIdx.x & 31;
    if (lane == 0) red[warp] = s;
    __syncthreads();
    if (threadIdx.x < 16) {
        float v = red[threadIdx.x];
#pragma unroll
        for (int o = 8; o; o >>= 1) v += __shfl_xor_sync(0xffffu, v, o);
        if (threadIdx.x == 0) g_n[l] = v;
    }
}

// ---------------------------------------------------------------- new codebooks + loss
__global__ void k_cb(const float* __restrict__ ema_w,
                     float* __restrict__ out_cb,
                     float* __restrict__ out_loss) {
    const int i = blockIdx.x * blockDim.x + threadIdx.x;
    if (i == 0) {
        double L = (0.25 * g_loss_acc[0] + 0.5 * g_loss_acc[1] + 1.0 * g_loss_acc[2])
                   * (1.0 / ((double)NTOK * (double)DIM));
        *out_loss = (float)L;
    }
    if (i >= NLEV * KCODES * DIM) return;
    const int row = i >> 10;   // / DIM
    const int l   = row >> 9;  // / KCODES
    float w  = DECAY * ema_w[i] + OMD * g_sums[i];
    float cs = g_cs[row];
    float n  = g_n[l];
    float csn = (cs + EPSV) / (n + 0.00512f) * n;   // K*EPS = 512e-5
    out_cb[i] = w / csn;
}

// ---------------------------------------------------------------- launch
extern "C" void kernel_launch(void* const* d_in, const int* in_sizes, int n_in,
                              void* d_out, int out_size) {
    const float* z_e         = (const float*)d_in[0];
    const float* codebooks   = (const float*)d_in[1];
    const float* ema_cluster = (const float*)d_in[2];
    const float* ema_w       = (const float*)d_in[3];
    float* out = (float*)d_out;

    const size_t ZQ = (size_t)NTOK * DIM;
    float* out_zq   = out;
    float* out_loss = out + ZQ;
    float* out_idx  = out + ZQ + 1;
    float* out_cb   = out + ZQ + 1 + (size_t)NLEV * NTOK;

    const int smem_bytes = (2 * ST_BUF + 2 * SC_BUF + 64) * (int)sizeof(float);
    cudaFuncSetAttribute(k_assign, cudaFuncAttributeMaxDynamicSharedMemorySize, smem_bytes);

    k_zero<<<(NLEV * KCODES * DIM + 255) / 256, 256>>>();
    k_c2<<<(NLEV * KCODES * 32 + 255) / 256, 256>>>(codebooks);
    for (int l = 0; l < NLEV; l++) {
        k_assign<<<NTOK / 64, 256, smem_bytes>>>(l, z_e, codebooks, out_idx);
        k_update<<<NTOK / 4, 256>>>(l, z_e, codebooks, out_zq);
    }
    k_csn<<<NLEV, 512>>>(ema_cluster);
    k_cb<<<(NLEV * KCODES * DIM + 255) / 256, 256>>>(ema_w, out_cb, out_loss);
}